// round 1
// baseline (speedup 1.0000x reference)
#include <cuda_runtime.h>
#include <math_constants.h>

// RMAC for x [64, 512, 32, 32] fp32 -> out [64, 512] (== [64,512,1,1])
//
// Region decomposition for H=W=32, L=3:
//   row/col ranges: R0=[0,32) R1=[0,21) R2=[11,32) R3=[0,16) R4=[8,24) R5=[16,32)
//   regions: (R0,R0) [weight 2: global pool + l=1 region], 2x2 over {R1,R2},
//            3x3 over {R3,R4,R5}  -> 14 region max vectors per batch.
// out[b,c] = sum_r w_r * M[b,r,c] / (||M[b,r,:]||_2 + 1e-6)

#define BATCH 64
#define CHAN  512
#define NREG  14
#define NRANGE 6

__device__ float g_M[BATCH * NREG * CHAN];  // region max scratch (1.75 MB)

__global__ __launch_bounds__(256) void rmac_stage1(const float* __restrict__ x) {
    const int warp_in_blk = threadIdx.x >> 5;
    const int lane        = threadIdx.x & 31;
    const int wid         = blockIdx.x * (blockDim.x >> 5) + warp_in_blk;  // (b,c) index
    const int b = wid >> 9;        // / CHAN
    const int c = wid & 511;       // % CHAN

    const float* __restrict__ p = x + (size_t)wid * 1024;  // 32x32 map, contiguous

    // 6 row-range max accumulators; lane == column index
    float m0 = -CUDART_INF_F, m1 = -CUDART_INF_F, m2 = -CUDART_INF_F;
    float m3 = -CUDART_INF_F, m4 = -CUDART_INF_F, m5 = -CUDART_INF_F;

#pragma unroll
    for (int k = 0; k < 32; ++k) {
        float v = p[k * 32 + lane];          // fully coalesced 128B per row
        m0 = fmaxf(m0, v);                   // [0,32)
        if (k < 21)            m1 = fmaxf(m1, v);   // [0,21)
        if (k >= 11)           m2 = fmaxf(m2, v);   // [11,32)
        if (k < 16)            m3 = fmaxf(m3, v);   // [0,16)
        if (k >= 8 && k < 24)  m4 = fmaxf(m4, v);   // [8,24)
        if (k >= 16)           m5 = fmaxf(m5, v);   // [16,32)
    }

    // per-warp smem: rowmax[range][col]
    __shared__ float smem[8][NRANGE * 32];   // 8 warps @ 256 threads
    float* ws = smem[warp_in_blk];
    ws[0 * 32 + lane] = m0;
    ws[1 * 32 + lane] = m1;
    ws[2 * 32 + lane] = m2;
    ws[3 * 32 + lane] = m3;
    ws[4 * 32 + lane] = m4;
    ws[5 * 32 + lane] = m5;
    __syncwarp();

    if (lane < NREG) {
        // region r -> (row-range, col-range)
        const int rr[NREG] = {0, 1,1,2,2, 3,3,3,4,4,4,5,5,5};
        const int cr[NREG] = {0, 1,2,1,2, 3,4,5,3,4,5,3,4,5};
        const int rs[NRANGE] = {0, 0, 11, 0, 8, 16};
        const int re[NRANGE] = {32, 21, 32, 16, 24, 32};
        const int R  = rr[lane];
        const int Cc = cr[lane];
        float mm = -CUDART_INF_F;
        for (int j = rs[Cc]; j < re[Cc]; ++j)
            mm = fmaxf(mm, ws[R * 32 + j]);
        g_M[(b * NREG + lane) * CHAN + c] = mm;
    }
}

__global__ __launch_bounds__(CHAN) void rmac_stage2(float* __restrict__ out) {
    const int b    = blockIdx.x;
    const int tid  = threadIdx.x;          // 0..511 == channel
    const int warp = tid >> 5;
    const int lane = tid & 31;

    __shared__ float s_inv[NREG];          // 1 / (norm + eps)

    if (warp < NREG) {
        const float* __restrict__ row = g_M + (b * NREG + warp) * CHAN;
        float s = 0.f;
#pragma unroll
        for (int c = lane; c < CHAN; c += 32) {
            float v = row[c];
            s += v * v;
        }
#pragma unroll
        for (int o = 16; o; o >>= 1)
            s += __shfl_down_sync(0xffffffffu, s, o);
        if (lane == 0)
            s_inv[warp] = 1.0f / (sqrtf(s) + 1e-6f);
    }
    __syncthreads();

    float acc = 0.f;
#pragma unroll
    for (int r = 0; r < NREG; ++r) {
        float w = (r == 0) ? 2.0f : 1.0f;
        acc += w * g_M[(b * NREG + r) * CHAN + tid] * s_inv[r];
    }
    out[b * CHAN + tid] = acc;
}

extern "C" void kernel_launch(void* const* d_in, const int* in_sizes, int n_in,
                              void* d_out, int out_size) {
    const float* x = (const float*)d_in[0];
    float* out = (float*)d_out;

    // 64*512 = 32768 warps, 8 warps/block -> 4096 blocks
    rmac_stage1<<<4096, 256>>>(x);
    rmac_stage2<<<BATCH, CHAN>>>(out);
}

// round 2
// speedup vs baseline: 1.1306x; 1.1306x over previous
#include <cuda_runtime.h>
#include <math_constants.h>

// RMAC for x [64, 512, 32, 32] fp32 -> out [64, 512, 1, 1]
//
// Row/col ranges for H=W=32, L=3:
//   R0=[0,32) R1=[0,21) R2=[11,32) R3=[0,16) R4=[8,24) R5=[16,32)
// 14 regions: (R0,R0) w=2 (global pool + l=1), 2x2 over {R1,R2}, 3x3 over {R3,R4,R5}.
// out[b,c] = sum_r w_r * M[b,r,c] / (||M[b,r,:]|| + 1e-6)

#define BATCH 64
#define CHAN  512
#define NREG  14

__device__ float g_M[BATCH * NREG * CHAN];  // region max scratch (1.75 MB)

__device__ __forceinline__ float4 fmax4(float4 a, float4 b) {
    return make_float4(fmaxf(a.x, b.x), fmaxf(a.y, b.y),
                       fmaxf(a.z, b.z), fmaxf(a.w, b.w));
}

// Warp per (b,c) feature map. Lane l: q = l>>3 (row phase), c0 = l&7 (4-col group).
// Iteration k (0..7): float4 at element k*128 + l*4 -> row 4k+q, cols 4c0..4c0+3.
// 8x LDG.128 per lane, each warp-level load touches 4 cache lines (coalesced).
__global__ __launch_bounds__(256, 3) void rmac_stage1(const float4* __restrict__ x) {
    const int w    = threadIdx.x >> 5;
    const int lane = threadIdx.x & 31;
    const int wid  = blockIdx.x * 8 + w;     // (b,c) map index
    const int q    = lane >> 3;
    const int c0   = lane & 7;

    const float4* __restrict__ p = x + (size_t)wid * 256 + lane;

    float4 v0 = p[0],   v1 = p[32],  v2 = p[64],  v3 = p[96];
    float4 v4 = p[128], v5 = p[160], v6 = p[192], v7 = p[224];

    // Primitive row-group maxes (per-lane, over this lane's rows 4k+q):
    float4 pc = fmax4(v2, v3);                 // rows [8,16)
    float4 pd = fmax4(v4, v5);                 // rows [16,24)
    float4 g3 = fmax4(fmax4(v0, v1), pc);      // rows [0,16)
    float4 g5 = fmax4(pd, fmax4(v6, v7));      // rows [16,32)
    float4 pb = (q == 3) ? pc : v3;            // rows [11,16): row 11 is k=2,q=3
    float4 pa = (q == 0) ? pd : v4;            // rows [16,21): row 20 is k=5,q=0

    float4 m[6];
    m[0] = fmax4(g3, g5);   // [0,32)
    m[1] = fmax4(g3, pa);   // [0,21)
    m[2] = fmax4(pb, g5);   // [11,32)
    m[3] = g3;              // [0,16)
    m[4] = fmax4(pc, pd);   // [8,24)
    m[5] = g5;              // [16,32)

    __shared__ float s1[8][6][4][32];   // [warp][range][q][col]
    __shared__ float s2[8][6][34];      // padded: bank = (2R + j) % 32, conflict-free

#pragma unroll
    for (int r = 0; r < 6; ++r)
        *(float4*)&s1[w][r][q][c0 << 2] = m[r];
    __syncwarp();

    // Cross-q reduce: lane = column j; true column max per row-range.
#pragma unroll
    for (int r = 0; r < 6; ++r) {
        float a = fmaxf(fmaxf(s1[w][r][0][lane], s1[w][r][1][lane]),
                        fmaxf(s1[w][r][2][lane], s1[w][r][3][lane]));
        s2[w][r][lane] = a;
    }
    __syncwarp();

    // 14 lanes: one region each = max over its column range of its row-range maxes.
    if (lane < NREG) {
        int R, Cc;
        if (lane == 0)     { R = 0; Cc = 0; }
        else if (lane < 5) { R = 1 + ((lane - 1) >> 1); Cc = 1 + ((lane - 1) & 1); }
        else               { int t = lane - 5; R = 3 + t / 3; Cc = 3 + t % 3; }
        const int cs = (Cc == 2) ? 11 : (Cc == 4) ? 8 : (Cc == 5) ? 16 : 0;
        const int ce = (Cc == 1) ? 21 : (Cc == 3) ? 16 : (Cc == 4) ? 24 : 32;
        float mm = -CUDART_INF_F;
        for (int j = cs; j < ce; ++j)
            mm = fmaxf(mm, s2[w][R][j]);
        const int b = wid >> 9, c = wid & 511;
        g_M[(b * NREG + lane) * CHAN + c] = mm;
    }
}

__global__ __launch_bounds__(CHAN) void rmac_stage2(float* __restrict__ out) {
    const int b    = blockIdx.x;
    const int tid  = threadIdx.x;          // channel
    const int warp = tid >> 5;
    const int lane = tid & 31;

    __shared__ float s_inv[NREG];

    if (warp < NREG) {
        const float4* __restrict__ row =
            (const float4*)(g_M + (b * NREG + warp) * CHAN);
        float s = 0.f;
#pragma unroll
        for (int i = 0; i < 4; ++i) {
            float4 v = row[lane + 32 * i];
            s += v.x * v.x + v.y * v.y + v.z * v.z + v.w * v.w;
        }
#pragma unroll
        for (int o = 16; o; o >>= 1)
            s += __shfl_down_sync(0xffffffffu, s, o);
        if (lane == 0)
            s_inv[warp] = 1.0f / (sqrtf(s) + 1e-6f);
    }
    __syncthreads();

    float acc = 0.f;
#pragma unroll
    for (int r = 0; r < NREG; ++r) {
        float wgt = (r == 0) ? 2.0f : 1.0f;
        acc += wgt * g_M[(b * NREG + r) * CHAN + tid] * s_inv[r];
    }
    out[b * CHAN + tid] = acc;
}

extern "C" void kernel_launch(void* const* d_in, const int* in_sizes, int n_in,
                              void* d_out, int out_size) {
    const float4* x = (const float4*)d_in[0];
    float* out = (float*)d_out;

    rmac_stage1<<<4096, 256>>>(x);      // 32768 warps = one per (b,c) map
    rmac_stage2<<<BATCH, CHAN>>>(out);
}